// round 1
// baseline (speedup 1.0000x reference)
#include <cuda_runtime.h>
#include <math.h>

// Problem constants
#define B_     4
#define T_     16
#define D_     512
#define HP_    24
#define WPD_   24
#define S_     (HP_*WPD_)     // 576
#define NSEQ_  (B_*S_)        // 2304
#define M_     (T_*NSEQ_)     // 36864
#define NH_    8
#define HD_    64
#define DQ_    128
#define GAMMA_ 0.1f

// Scratch (allocation-free rule: __device__ globals)
__device__ float g_Q  [(size_t)M_*D_];
__device__ float g_K  [(size_t)M_*D_];
__device__ float g_V  [(size_t)M_*D_];
__device__ float g_HDN[(size_t)M_*DQ_];
__device__ float g_PV [M_];
__device__ float g_AO [(size_t)M_*D_];
__device__ float g_O2 [(size_t)M_*D_];

// ---------------------------------------------------------------------------
// Tiled fp32 GEMM: C[m, j] = act( A[m, :] @ W[:, j] + bias[j] )
//   GATHER=1: A[m,d] gathered from 5D (B,T,D,Hp,Wp); m = t*NSEQ + n
//   GATHER=0: A = g_AO row-major (M x 512), C = g_O2
// BM=BN=128, BK=8, 256 threads, 8x8 per thread, double-buffered smem.
// ---------------------------------------------------------------------------
template<int GATHER, int ACT>
__global__ __launch_bounds__(256, 2) void gemm_kernel(
    const float* __restrict__ Ain, const float* __restrict__ W,
    const float* __restrict__ bias, int which, int ncols)
{
    constexpr int BM = 128, BN = 128, BK = 8;
    __shared__ float As[2][BK][BM];
    __shared__ float Bs[2][BK][BN];

    const int tid = threadIdx.x;
    const int m0  = blockIdx.y * BM;
    const int j0  = blockIdx.x * BN;

    const float* A = GATHER ? Ain : g_AO;
    float* C;
    if (GATHER) C = (which == 0) ? g_Q : (which == 1) ? g_K : (which == 2) ? g_V : g_HDN;
    else        C = g_O2;

    // ---- A loader setup ----
    int aM, aK0;
    size_t aOff;
    if (GATHER) {
        aM  = tid & 127;
        aK0 = (tid >> 7) * 4;
        int m = m0 + aM;
        int t = m / NSEQ_, n = m % NSEQ_;
        int b = n / S_,    sp = n % S_;
        aOff = ((size_t)(b * T_ + t) * D_) * S_ + sp;   // element d at aOff + d*S_
    } else {
        aM  = tid >> 1;
        aK0 = (tid & 1) * 4;
        aOff = (size_t)(m0 + aM) * D_ + aK0;            // float4 at aOff + k0
    }
    const int bJ = (tid & 31) * 4;
    const int bK = tid >> 5;

    float areg[4];
    float4 breg;

    const int ty = tid >> 4, tx = tid & 15;
    float acc[8][8];
    #pragma unroll
    for (int i = 0; i < 8; i++)
        #pragma unroll
        for (int j = 0; j < 8; j++) acc[i][j] = 0.f;

    // ---- prologue: load tile 0 into buffer 0 ----
    {
        if (GATHER) {
            #pragma unroll
            for (int i = 0; i < 4; i++) areg[i] = __ldg(&A[aOff + (size_t)(aK0 + i) * S_]);
        } else {
            float4 v = *reinterpret_cast<const float4*>(&A[aOff]);
            areg[0] = v.x; areg[1] = v.y; areg[2] = v.z; areg[3] = v.w;
        }
        breg = *reinterpret_cast<const float4*>(&W[(size_t)bK * ncols + j0 + bJ]);
        #pragma unroll
        for (int i = 0; i < 4; i++) As[0][aK0 + i][aM] = areg[i];
        *reinterpret_cast<float4*>(&Bs[0][bK][bJ]) = breg;
    }
    __syncthreads();

    const int KT = D_ / BK;   // 64
    for (int kt = 0; kt < KT; kt++) {
        const int cur = kt & 1;
        if (kt + 1 < KT) {
            const int k0 = (kt + 1) * BK;
            if (GATHER) {
                #pragma unroll
                for (int i = 0; i < 4; i++)
                    areg[i] = __ldg(&A[aOff + (size_t)(k0 + aK0 + i) * S_]);
            } else {
                float4 v = *reinterpret_cast<const float4*>(&A[aOff + k0]);
                areg[0] = v.x; areg[1] = v.y; areg[2] = v.z; areg[3] = v.w;
            }
            breg = *reinterpret_cast<const float4*>(&W[(size_t)(k0 + bK) * ncols + j0 + bJ]);
        }
        #pragma unroll
        for (int k = 0; k < BK; k++) {
            float4 a0 = *reinterpret_cast<const float4*>(&As[cur][k][ty * 8]);
            float4 a1 = *reinterpret_cast<const float4*>(&As[cur][k][ty * 8 + 4]);
            float4 b0 = *reinterpret_cast<const float4*>(&Bs[cur][k][tx * 8]);
            float4 b1 = *reinterpret_cast<const float4*>(&Bs[cur][k][tx * 8 + 4]);
            float a[8] = {a0.x, a0.y, a0.z, a0.w, a1.x, a1.y, a1.z, a1.w};
            float b[8] = {b0.x, b0.y, b0.z, b0.w, b1.x, b1.y, b1.z, b1.w};
            #pragma unroll
            for (int i = 0; i < 8; i++)
                #pragma unroll
                for (int j = 0; j < 8; j++) acc[i][j] = fmaf(a[i], b[j], acc[i][j]);
        }
        if (kt + 1 < KT) {
            const int nxt = cur ^ 1;
            #pragma unroll
            for (int i = 0; i < 4; i++) As[nxt][aK0 + i][aM] = areg[i];
            *reinterpret_cast<float4*>(&Bs[nxt][bK][bJ]) = breg;
            __syncthreads();
        }
    }

    // ---- epilogue: bias (+gelu), row-major store ----
    #pragma unroll
    for (int i = 0; i < 8; i++) {
        const int m = m0 + ty * 8 + i;
        const size_t rowp = (size_t)m * ncols + j0 + tx * 8;
        #pragma unroll
        for (int j = 0; j < 8; j++) {
            float v = acc[i][j] + bias[j0 + tx * 8 + j];
            if (ACT == 1) v = v * normcdff(v);   // exact GELU: x * Phi(x)
            C[rowp + j] = v;
        }
    }
}

// ---------------------------------------------------------------------------
// Penalty: p_viol[m] = sigmoid( dot(g_HDN[m, 0:128], Wp2) + bp2 )
// One warp per row.
// ---------------------------------------------------------------------------
__global__ __launch_bounds__(256) void pviol_kernel(
    const float* __restrict__ Wp2, const float* __restrict__ bp2)
{
    const int warp = (blockIdx.x * blockDim.x + threadIdx.x) >> 5;
    const int lane = threadIdx.x & 31;
    if (warp >= M_) return;
    float4 v = reinterpret_cast<const float4*>(g_HDN + (size_t)warp * DQ_)[lane];
    float4 w = reinterpret_cast<const float4*>(Wp2)[lane];
    float acc = v.x * w.x + v.y * w.y + v.z * w.z + v.w * w.w;
    #pragma unroll
    for (int o = 16; o; o >>= 1) acc += __shfl_xor_sync(0xFFFFFFFFu, acc, o);
    if (lane == 0) {
        float x = acc + bp2[0];
        g_PV[warp] = 1.f / (1.f + expf(-x));
    }
}

// ---------------------------------------------------------------------------
// Attention: one block per (h, n). T=16 keys/queries, hd=64.
// scores = QK^T/8 - GAMMA*pv[tk]; softmax over tk; out = attn @ V -> g_AO
// ---------------------------------------------------------------------------
__global__ __launch_bounds__(128) void attn_kernel()
{
    const int h = blockIdx.x;
    const int n = blockIdx.y;
    __shared__ float Qs[16 * 65], Ks[16 * 65], Vs[16 * 65];
    __shared__ float At[16 * 17];
    __shared__ float Pv[16];
    const int tid = threadIdx.x;

    #pragma unroll
    for (int i = 0; i < 8; i++) {
        int l = tid + i * 128;
        int t = l >> 6, e = l & 63;
        size_t src = ((size_t)(t * NSEQ_ + n)) * D_ + h * HD_ + e;
        Qs[t * 65 + e] = g_Q[src];
        Ks[t * 65 + e] = g_K[src];
        Vs[t * 65 + e] = g_V[src];
    }
    if (tid < 16) Pv[tid] = g_PV[tid * NSEQ_ + n];
    __syncthreads();

    #pragma unroll
    for (int i = 0; i < 2; i++) {
        int l = tid + i * 128;
        int tq = l >> 4, tk = l & 15;
        float acc = 0.f;
        #pragma unroll
        for (int e = 0; e < 64; e++) acc = fmaf(Qs[tq * 65 + e], Ks[tk * 65 + e], acc);
        At[tq * 17 + tk] = acc * 0.125f - GAMMA_ * Pv[tk];
    }
    __syncthreads();

    if (tid < 16) {
        float mx = -1e30f;
        #pragma unroll
        for (int k = 0; k < 16; k++) mx = fmaxf(mx, At[tid * 17 + k]);
        float sum = 0.f;
        #pragma unroll
        for (int k = 0; k < 16; k++) { float e = expf(At[tid * 17 + k] - mx); At[tid * 17 + k] = e; sum += e; }
        float inv = 1.f / sum;
        #pragma unroll
        for (int k = 0; k < 16; k++) At[tid * 17 + k] *= inv;
    }
    __syncthreads();

    #pragma unroll
    for (int i = 0; i < 8; i++) {
        int l = tid + i * 128;
        int tq = l >> 6, e = l & 63;
        float acc = 0.f;
        #pragma unroll
        for (int k = 0; k < 16; k++) acc = fmaf(At[tq * 17 + k], Vs[k * 65 + e], acc);
        g_AO[((size_t)(tq * NSEQ_ + n)) * D_ + h * HD_ + e] = acc;
    }
}

// ---------------------------------------------------------------------------
// Scatter: g_O2[t][n][j] -> out[(b,t,j,hp,wp)] via 32x32 smem transpose tiles.
// grid (D/32, NSEQ/32, T); n-tiles never cross b (576 % 32 == 0).
// ---------------------------------------------------------------------------
__global__ __launch_bounds__(256) void scatter_kernel(float* __restrict__ out)
{
    __shared__ float tile[32][33];
    const int jt = blockIdx.x;
    const int nt = blockIdx.y;
    const int t  = blockIdx.z;
    const int tx = threadIdx.x & 31, ty = threadIdx.x >> 5;

    #pragma unroll
    for (int p = 0; p < 4; p++) {
        int n = nt * 32 + ty + p * 8;
        tile[ty + p * 8][tx] = g_O2[((size_t)(t * NSEQ_ + n)) * D_ + jt * 32 + tx];
    }
    __syncthreads();

    const int n0 = nt * 32;
    const int b = n0 / S_, sp0 = n0 % S_;
    #pragma unroll
    for (int p = 0; p < 4; p++) {
        int j = jt * 32 + ty + p * 8;
        out[((size_t)((b * T_ + t) * D_ + j)) * S_ + sp0 + tx] = tile[tx][ty + p * 8];
    }
}

// ---------------------------------------------------------------------------
extern "C" void kernel_launch(void* const* d_in, const int* in_sizes, int n_in,
                              void* d_out, int out_size)
{
    const float* h_opt = (const float*)d_in[0];
    const float* h_sar = (const float*)d_in[1];
    const float* Wq  = (const float*)d_in[2];  const float* bq  = (const float*)d_in[3];
    const float* Wk  = (const float*)d_in[4];  const float* bk  = (const float*)d_in[5];
    const float* Wv  = (const float*)d_in[6];  const float* bv  = (const float*)d_in[7];
    const float* Wo  = (const float*)d_in[8];  const float* bo  = (const float*)d_in[9];
    const float* Wp1 = (const float*)d_in[10]; const float* bp1 = (const float*)d_in[11];
    const float* Wp2 = (const float*)d_in[12]; const float* bp2 = (const float*)d_in[13];
    float* out = (float*)d_out;

    dim3 blk(256);
    dim3 grid512(D_ / 128, M_ / 128);   // (4, 288)
    dim3 grid128(DQ_ / 128, M_ / 128);  // (1, 288)

    // Projections (gathered A)
    gemm_kernel<1, 0><<<grid512, blk>>>(h_opt, Wq,  bq,  0, D_);
    gemm_kernel<1, 0><<<grid512, blk>>>(h_sar, Wk,  bk,  1, D_);
    gemm_kernel<1, 0><<<grid512, blk>>>(h_sar, Wv,  bv,  2, D_);
    gemm_kernel<1, 1><<<grid128, blk>>>(h_sar, Wp1, bp1, 3, DQ_);

    // Penalty MLP head
    pviol_kernel<<<M_ / 8, 256>>>(Wp2, bp2);

    // Fused attention
    attn_kernel<<<dim3(NH_, NSEQ_), 128>>>();

    // Output projection (plain A = g_AO)
    gemm_kernel<0, 0><<<grid512, blk>>>(nullptr, Wo, bo, 0, D_);

    // Scatter back to (B, T, D, Hp, Wp)
    scatter_kernel<<<dim3(D_ / 32, NSEQ_ / 32, T_), 256>>>(out);
}